// round 10
// baseline (speedup 1.0000x reference)
#include <cuda_runtime.h>
#include <math.h>

#define MDIM 512
#define LDIM 31
#define CTOT 542                 // MDIM + LDIM - 1
#define NX   1024
#define ROWE (NX * LDIM)         // 31744 floats per input row strip
#define XCE  (MDIM * LDIM)       // 15872 floats per H/out row strip

#define WC     64                // output columns per tile
#define NTILE  (MDIM / WC)       // 8
#define WCOLS  (2 * WC + 2)      // 130 input cols per window
#define YLEN   94                // outputs per tile (WC + LDIM - 1)
#define YPAD   96

// Static scratch (zero-initialized at module load; counters self-reset)
__device__ float    g_ynp[NTILE * MDIM * YPAD]; // per-tile partial yn
__device__ float    g_yn[MDIM * CTOT];
__device__ float    g_rmax1[MDIM];
__device__ float    g_rmax2[MDIM];
__device__ unsigned g_cnt[MDIM];                // per-row tile arrival counters

__device__ __forceinline__ float blockReduceMax(float v, float* sred) {
    __syncthreads();
    int lane = threadIdx.x & 31, wid = threadIdx.x >> 5;
    int nw = blockDim.x >> 5;
    #pragma unroll
    for (int o = 16; o; o >>= 1) v = fmaxf(v, __shfl_xor_sync(0xffffffffu, v, o));
    if (lane == 0) sred[wid] = v;
    __syncthreads();
    if (wid == 0) {
        float x = (lane < nw) ? sred[lane] : -INFINITY;
        #pragma unroll
        for (int o = 16; o; o >>= 1) x = fmaxf(x, __shfl_xor_sync(0xffffffffu, x, o));
        if (lane == 0) sred[0] = x;
    }
    __syncthreads();
    return sred[0];
}

// ---------------------------------------------------------------------------
// Forward: one block per (tile, row). The LAST tile block of each row also
// combines the 8 partials into yn + per-row max (deterministic fixed-order
// sum), eliminating the separate k_max kernel.
// ---------------------------------------------------------------------------
__global__ void __launch_bounds__(256, 6) k_fwd(const float* __restrict__ X,
                                                const float* __restrict__ H) {
    __shared__ float sLam[WCOLS * 32];   // 130 x 32 = 16.25 KB
    __shared__ float sP[WC * 33];        // 64 x 33 = 8.25 KB (conflict-free skew)
    __shared__ float sred[32];
    __shared__ unsigned lastFlag;

    const int t = blockIdx.x, r = blockIdx.y;
    const int tid = threadIdx.x;
    const int lane = tid & 31, warp = tid >> 5;     // 8 warps
    const int c0 = t * WC;
    const int baseCol = 2 * c0 - 1;

    // Row-resize taps ([1/8,3/8,3/8,1/8], renormalized at edges)
    float w0, w1, w2, w3; int i0, i1, i2, i3;
    if (r == 0) {
        w0 = 0.f;     w1 = 3.f/7.f; w2 = 3.f/7.f; w3 = 1.f/7.f;
        i0 = 0; i1 = 0; i2 = 1; i3 = 2;
    } else if (r == MDIM - 1) {
        w0 = 1.f/7.f; w1 = 3.f/7.f; w2 = 3.f/7.f; w3 = 0.f;
        i0 = 2*r - 1; i1 = 2*r; i2 = 2*r + 1; i3 = i2;
    } else {
        w0 = 0.125f;  w1 = 0.375f;  w2 = 0.375f;  w3 = 0.125f;
        i0 = 2*r - 1; i1 = 2*r; i2 = 2*r + 1; i3 = 2*r + 2;
    }
    const float* X0 = X + (size_t)i0 * ROWE;
    const float* X1 = X + (size_t)i1 * ROWE;
    const float* X2p = X + (size_t)i2 * ROWE;
    const float* X3 = X + (size_t)i3 * ROWE;
    const float* Hr = H + (size_t)r * XCE;

    // Phase A: row-combine + lambda-conv via warp shuffles (lane = lambda idx).
    for (int col = warp; col < WCOLS; col += 8) {
        int ic = baseCol + col;
        float x = 0.f;
        if (lane < LDIM && ic >= 0 && ic < NX) {
            int g = ic * LDIM + lane;
            x = w0 * __ldg(X0 + g) + w1 * __ldg(X1 + g)
              + w2 * __ldg(X2p + g) + w3 * __ldg(X3 + g);
        }
        float xm = __shfl_up_sync(0xffffffffu, x, 1);
        float xp = __shfl_down_sync(0xffffffffu, x, 1);
        float v = 0.5f * x;
        if (lane > 0)         v += 0.25f * xm;
        if (lane < LDIM - 1)  v += 0.25f * xp;
        sLam[col * 32 + lane] = v;           // lane 31 stores dead pad
    }
    __syncthreads();

    // Phase B: 4-tap column resize + H multiply -> sP (stride 33).
    {
        const int l = lane, dc0 = warp;
        if (l < LDIM) {
            #pragma unroll
            for (int q = 0; q < 8; ++q) {
                int dc = dc0 + q * 8;            // 0..63
                int c = c0 + dc;
                float v;
                if (c == 0) {
                    v = (3.f/7.f)*sLam[1*32 + l] + (3.f/7.f)*sLam[2*32 + l]
                      + (1.f/7.f)*sLam[3*32 + l];
                } else if (c == MDIM - 1) {
                    v = (1.f/7.f)*sLam[126*32 + l] + (3.f/7.f)*sLam[127*32 + l]
                      + (3.f/7.f)*sLam[128*32 + l];
                } else {
                    int b = 2 * dc * 32 + l;
                    v = 0.125f*sLam[b]      + 0.375f*sLam[b + 32]
                      + 0.375f*sLam[b + 64] + 0.125f*sLam[b + 96];
                }
                sP[dc * 33 + l] = __ldg(Hr + c * LDIM + l) * v;
            }
        }
    }
    __syncthreads();

    // Phase D: skewed partial sums for this tile (deterministic, no atomics).
    if (tid < YLEN) {
        int lcc = tid;
        int ilo = lcc - (WC - 1); if (ilo < 0) ilo = 0;
        int ihi = (lcc < LDIM - 1) ? lcc : (LDIM - 1);
        float acc = 0.f;
        for (int i = ilo; i <= ihi; ++i)
            acc += sP[(lcc - i) * 33 + i];     // bank-conflict-free (stride 33)
        g_ynp[(t * MDIM + r) * YPAD + lcc] = acc;
    }
    __syncthreads();
    __threadfence();                            // publish partials

    // Last-arriving tile block combines the row (fixed-order sum: deterministic)
    if (tid == 0)
        lastFlag = (atomicAdd(&g_cnt[r], 1u) == NTILE - 1) ? 1u : 0u;
    __syncthreads();
    if (lastFlag) {
        float lmax = -INFINITY;
        for (int cc = tid; cc < CTOT; cc += 256) {
            int thi = cc >> 6; if (thi > NTILE - 1) thi = NTILE - 1;
            int tlo = (cc - 30) >> 6; if (tlo < 0) tlo = 0;  // ceil((cc-93)/64)
            float s = 0.f;
            for (int t2 = tlo; t2 <= thi; ++t2)
                s += g_ynp[(t2 * MDIM + r) * YPAD + (cc - (t2 << 6))];
            g_yn[r * CTOT + cc] = s;
            lmax = fmaxf(lmax, s);
        }
        float bm = blockReduceMax(lmax, sred);
        if (tid == 0) { g_rmax1[r] = bm; g_cnt[r] = 0u; }  // reset for replay
    }
}

// Build zero-padded residual sE[0..CTOT+1] (sE[0]=sE[CTOT+1]=0, sE[1+c]=res[c])
// and its full lambda-conv s2[c] (zero-extended ends).
__device__ __forceinline__ void buildResidual(const float* __restrict__ y, int r,
                                              float invY, float* sE, float* s2) {
    const float* ynr = g_yn + r * CTOT;
    const float* yr  = y + r * CTOT;
    const int tid = threadIdx.x, nt = blockDim.x;
    if (tid == 0) { sE[0] = 0.f; sE[CTOT + 1] = 0.f; }
    for (int cc = tid; cc < CTOT; cc += nt)
        sE[cc + 1] = ynr[cc] * invY - yr[cc];
    __syncthreads();
    for (int cc = tid; cc < CTOT; cc += nt)
        s2[cc] = 0.25f * (sE[cc] + sE[cc + 2]) + 0.5f * sE[cc + 1];
    __syncthreads();
}

// ---------------------------------------------------------------------------
// Backward pass 1: per-row max of X2. Lane = lambda index i (coalesced 124B
// H rows per warp; s2/sE accesses conflict-free; corrections lane-constant).
// ---------------------------------------------------------------------------
__global__ void __launch_bounds__(512) k_bwd1(const float* __restrict__ y,
                                              const float* __restrict__ H) {
    __shared__ float sE[CTOT + 2];
    __shared__ float s2[CTOT];
    __shared__ float sred[32];
    const int r = blockIdx.x, tid = threadIdx.x;
    const int lane = tid & 31, w = tid >> 5;        // 16 warps

    float v0 = (tid < MDIM) ? g_rmax1[tid] : -INFINITY;
    const float invY = 1.0f / blockReduceMax(v0, sred);
    buildResidual(y, r, invY, sE, s2);

    const float* Hr = H + (size_t)r * XCE;
    float lmax = -INFINITY;
    if (lane < LDIM) {
        #pragma unroll 4
        for (int m = w; m < MDIM; m += 16) {
            float v = s2[m + lane];
            if (lane == 0)        v -= 0.25f * sE[m];
            if (lane == LDIM - 1) v -= 0.25f * sE[m + 32];
            lmax = fmaxf(lmax, __ldg(Hr + m * LDIM + lane) * v);
        }
    }
    float bm = blockReduceMax(lmax, sred);
    if (tid == 0) g_rmax2[r] = bm;
}

// ---------------------------------------------------------------------------
// Backward pass 2: recompute X2 (H L2-resident), write normalized output.
// ---------------------------------------------------------------------------
__global__ void __launch_bounds__(512) k_bwd2(const float* __restrict__ y,
                                              const float* __restrict__ H,
                                              float* __restrict__ out) {
    __shared__ float sE[CTOT + 2];
    __shared__ float s2[CTOT];
    __shared__ float sred[32];
    const int r = blockIdx.x, tid = threadIdx.x;
    const int lane = tid & 31, w = tid >> 5;        // 16 warps

    float v0 = (tid < MDIM) ? g_rmax1[tid] : -INFINITY;
    const float invY = 1.0f / blockReduceMax(v0, sred);
    float v1 = (tid < MDIM) ? g_rmax2[tid] : -INFINITY;
    const float invO = 1.0f / blockReduceMax(v1, sred);
    buildResidual(y, r, invY, sE, s2);

    const float* Hr   = H   + (size_t)r * XCE;
    float*       outr = out + (size_t)r * XCE;
    if (lane < LDIM) {
        #pragma unroll 4
        for (int m = w; m < MDIM; m += 16) {
            float v = s2[m + lane];
            if (lane == 0)        v -= 0.25f * sE[m];
            if (lane == LDIM - 1) v -= 0.25f * sE[m + 32];
            outr[m * LDIM + lane] = (__ldg(Hr + m * LDIM + lane) * v) * invO;
        }
    }
}

extern "C" void kernel_launch(void* const* d_in, const int* in_sizes, int n_in,
                              void* d_out, int out_size) {
    const float *X = 0, *y = 0, *H = 0;
    for (int i = 0; i < n_in; ++i) {
        if      (in_sizes[i] == NX * NX * LDIM)     X = (const float*)d_in[i];
        else if (in_sizes[i] == MDIM * CTOT)        y = (const float*)d_in[i];
        else if (in_sizes[i] == MDIM * MDIM * LDIM) H = (const float*)d_in[i];
    }
    if (!X || !y || !H) {
        X = (const float*)d_in[0];
        y = (const float*)d_in[1];
        H = (const float*)d_in[2];
    }
    float* out = (float*)d_out;

    dim3 gf(NTILE, MDIM);
    k_fwd <<<gf, 256>>>(X, H);
    k_bwd1<<<MDIM, 512>>>(y, H);
    k_bwd2<<<MDIM, 512>>>(y, H, out);
}

// round 12
// speedup vs baseline: 1.1277x; 1.1277x over previous
#include <cuda_runtime.h>
#include <math.h>

#define MDIM 512
#define LDIM 31
#define CTOT 542                 // MDIM + LDIM - 1
#define NX   1024
#define ROWE (NX * LDIM)         // 31744 floats per input row strip
#define ROW4 (ROWE / 4)          // 7936 float4 per row strip
#define XCE  (MDIM * LDIM)       // 15872 floats per H/out row strip
#define XC4  (XCE / 4)           // 3968 float4 per row

#define WC     64                // output columns per tile
#define NTILE  (MDIM / WC)       // 8
#define WCOLS  (2 * WC + 2)      // 130 input cols per window
#define WF4    1008              // float4 loads per stream (4032 floats >= 1+4030)
#define YLEN   94                // outputs per tile (WC + LDIM - 1)
#define YPAD   96

// Static scratch
__device__ float g_ynp[NTILE * MDIM * YPAD]; // per-tile partial yn
__device__ float g_yn[MDIM * CTOT];
__device__ float g_rmax1[MDIM];
__device__ float g_rmax2[MDIM];

__device__ __forceinline__ float blockReduceMax(float v, float* sred) {
    __syncthreads();
    int lane = threadIdx.x & 31, wid = threadIdx.x >> 5;
    int nw = blockDim.x >> 5;
    #pragma unroll
    for (int o = 16; o; o >>= 1) v = fmaxf(v, __shfl_xor_sync(0xffffffffu, v, o));
    if (lane == 0) sred[wid] = v;
    __syncthreads();
    if (wid == 0) {
        float x = (lane < nw) ? sred[lane] : -INFINITY;
        #pragma unroll
        for (int o = 16; o; o >>= 1) x = fmaxf(x, __shfl_xor_sync(0xffffffffu, x, o));
        if (lane == 0) sred[0] = x;
    }
    __syncthreads();
    return sred[0];
}

// ---------------------------------------------------------------------------
// Forward: one block per (tile, row). The window (130 cols x 31) is a
// CONTIGUOUS 4030-float span of the X row strip, and its start is always
// ≡1 (mod 4), so Phase A streams it with aligned float4 loads (deep MLP),
// combining the 4 resize rows at load time. Phase A2 does λ+transpose via
// shuffles from SMEM. sP aliases the raw buffer (dead after A2).
// ---------------------------------------------------------------------------
__global__ void __launch_bounds__(256, 6) k_fwd(const float* __restrict__ X,
                                                const float* __restrict__ H) {
    __shared__ float4 sBuf4[WF4];        // 16.1 KB: raw window, then sP alias
    __shared__ float  sLam[WCOLS * 32];  // 16.6 KB: lambda'd, transposed window
    float* sRaw = (float*)sBuf4;         // sRaw[1 + k] = window elem k
    float* sP   = (float*)sBuf4;         // 64 x 33 = 2112 floats (fits)

    const int t = blockIdx.x, r = blockIdx.y;
    const int tid = threadIdx.x;
    const int lane = tid & 31, warp = tid >> 5;     // 8 warps

    // Row-resize taps ([1/8,3/8,3/8,1/8], renormalized at edges)
    float w0, w1, w2, w3; int i0, i1, i2, i3;
    if (r == 0) {
        w0 = 0.f;     w1 = 3.f/7.f; w2 = 3.f/7.f; w3 = 1.f/7.f;
        i0 = 0; i1 = 0; i2 = 1; i3 = 2;
    } else if (r == MDIM - 1) {
        w0 = 1.f/7.f; w1 = 3.f/7.f; w2 = 3.f/7.f; w3 = 0.f;
        i0 = 2*r - 1; i1 = 2*r; i2 = 2*r + 1; i3 = i2;
    } else {
        w0 = 0.125f;  w1 = 0.375f;  w2 = 0.375f;  w3 = 0.125f;
        i0 = 2*r - 1; i1 = 2*r; i2 = 2*r + 1; i3 = 2*r + 2;
    }
    const float4* X0 = (const float4*)(X + (size_t)i0 * ROWE);
    const float4* X1 = (const float4*)(X + (size_t)i1 * ROWE);
    const float4* X2p = (const float4*)(X + (size_t)i2 * ROWE);
    const float4* X3 = (const float4*)(X + (size_t)i3 * ROWE);
    const float* Hr = H + (size_t)r * XCE;

    // Phase A: vectorized row-combine of the contiguous window.
    // Window floats: [gb, gb+4030), gb = (128t-1)*31 = 3968t-31 ≡ 1 (mod 4).
    // Aligned base gb0 = gb-1 -> j0 = gb0/4 = 992t-8. Out-of-range float4s
    // (first 8 at t=0, last 8 at t=7) are exactly aligned -> full zero-fill.
    {
        const int j0 = 992 * t - 8;
        for (int j = tid; j < WF4; j += 256) {
            int g4 = j0 + j;
            float4 o = make_float4(0.f, 0.f, 0.f, 0.f);
            if (g4 >= 0 && g4 < ROW4) {
                float4 a = __ldg(X0 + g4), b = __ldg(X1 + g4);
                float4 c = __ldg(X2p + g4), d = __ldg(X3 + g4);
                o.x = w0*a.x + w1*b.x + w2*c.x + w3*d.x;
                o.y = w0*a.y + w1*b.y + w2*c.y + w3*d.y;
                o.z = w0*a.z + w1*b.z + w2*c.z + w3*d.z;
                o.w = w0*a.w + w1*b.w + w2*c.w + w3*d.w;
            }
            sBuf4[j] = o;
        }
    }
    __syncthreads();

    // Phase A2: lambda conv [1/4,1/2,1/4] + transpose to stride-32 layout.
    // Out-of-range cols are zero in sRaw, matching the old explicit guard.
    for (int col = warp; col < WCOLS; col += 8) {
        float x = (lane < LDIM) ? sRaw[1 + col * LDIM + lane] : 0.f;
        float xm = __shfl_up_sync(0xffffffffu, x, 1);
        float xp = __shfl_down_sync(0xffffffffu, x, 1);
        float v = 0.5f * x;
        if (lane > 0)         v += 0.25f * xm;
        if (lane < LDIM - 1)  v += 0.25f * xp;
        sLam[col * 32 + lane] = v;
    }
    __syncthreads();

    // Phase B: 4-tap column resize + H multiply -> sP (stride 33, aliases sRaw).
    {
        const int c0 = t * WC;
        const int l = lane, dc0 = warp;
        if (l < LDIM) {
            #pragma unroll
            for (int q = 0; q < 8; ++q) {
                int dc = dc0 + q * 8;            // 0..63
                int c = c0 + dc;
                float v;
                if (c == 0) {
                    v = (3.f/7.f)*sLam[1*32 + l] + (3.f/7.f)*sLam[2*32 + l]
                      + (1.f/7.f)*sLam[3*32 + l];
                } else if (c == MDIM - 1) {
                    v = (1.f/7.f)*sLam[126*32 + l] + (3.f/7.f)*sLam[127*32 + l]
                      + (3.f/7.f)*sLam[128*32 + l];
                } else {
                    int b = 2 * dc * 32 + l;
                    v = 0.125f*sLam[b]      + 0.375f*sLam[b + 32]
                      + 0.375f*sLam[b + 64] + 0.125f*sLam[b + 96];
                }
                sP[dc * 33 + l] = __ldg(Hr + c * LDIM + l) * v;
            }
        }
    }
    __syncthreads();

    // Phase D: skewed partial sums for this tile (deterministic, no atomics).
    if (tid < YLEN) {
        int lcc = tid;
        int ilo = lcc - (WC - 1); if (ilo < 0) ilo = 0;
        int ihi = (lcc < LDIM - 1) ? lcc : (LDIM - 1);
        float acc = 0.f;
        for (int i = ilo; i <= ihi; ++i)
            acc += sP[(lcc - i) * 33 + i];     // bank-conflict-free (stride 33)
        g_ynp[(t * MDIM + r) * YPAD + lcc] = acc;
    }
}

// ---------------------------------------------------------------------------
// Combine tile partials -> yn row + per-row max.
// ---------------------------------------------------------------------------
__global__ void __launch_bounds__(256) k_max(void) {
    __shared__ float sred[32];
    const int r = blockIdx.x, tid = threadIdx.x;
    float lmax = -INFINITY;
    for (int cc = tid; cc < CTOT; cc += 256) {
        int thi = cc >> 6; if (thi > NTILE - 1) thi = NTILE - 1;
        int tlo = (cc - 30) >> 6; if (tlo < 0) tlo = 0;   // = max(0, ceil((cc-93)/64))
        float s = 0.f;
        for (int t2 = tlo; t2 <= thi; ++t2)
            s += g_ynp[(t2 * MDIM + r) * YPAD + (cc - (t2 << 6))];
        g_yn[r * CTOT + cc] = s;
        lmax = fmaxf(lmax, s);
    }
    float bm = blockReduceMax(lmax, sred);
    if (tid == 0) g_rmax1[r] = bm;
}

// Build zero-padded residual sE[0..CTOT+1] (sE[0]=sE[CTOT+1]=0, sE[1+c]=res[c])
// and its full lambda-conv s2[c] (zero-extended ends).
__device__ __forceinline__ void buildResidual(const float* __restrict__ y, int r,
                                              float invY, float* sE, float* s2) {
    const float* ynr = g_yn + r * CTOT;
    const float* yr  = y + r * CTOT;
    const int tid = threadIdx.x, nt = blockDim.x;
    if (tid == 0) { sE[0] = 0.f; sE[CTOT + 1] = 0.f; }
    for (int cc = tid; cc < CTOT; cc += nt)
        sE[cc + 1] = ynr[cc] * invY - yr[cc];
    __syncthreads();
    for (int cc = tid; cc < CTOT; cc += nt)
        s2[cc] = 0.25f * (sE[cc] + sE[cc + 2]) + 0.5f * sE[cc + 1];
    __syncthreads();
}

// X2 element: middle i -> s2[m+i]; boundary corrections via zero pads in sE.
__device__ __forceinline__ float x2val(const float* sE, const float* s2,
                                       int m, int i) {
    float v = s2[m + i];
    if (i == 0)        v -= 0.25f * sE[m];
    if (i == LDIM - 1) v -= 0.25f * sE[m + 32];
    return v;
}

// ---------------------------------------------------------------------------
// Backward pass 1: per-row max of X2 (float4-streamed H; H lands in L2).
// ---------------------------------------------------------------------------
__global__ void __launch_bounds__(512) k_bwd1(const float* __restrict__ y,
                                              const float* __restrict__ H) {
    __shared__ float sE[CTOT + 2];
    __shared__ float s2[CTOT];
    __shared__ float sred[32];
    const int r = blockIdx.x, tid = threadIdx.x;

    float v0 = (tid < MDIM) ? g_rmax1[tid] : -INFINITY;
    const float invY = 1.0f / blockReduceMax(v0, sred);
    buildResidual(y, r, invY, sE, s2);

    const float4* H4 = (const float4*)(H + (size_t)r * XCE);
    float lmax = -INFINITY;
    for (int j = tid; j < XC4; j += 512) {
        float4 h = __ldg(H4 + j);
        int e = j * 4;
        int m = e / LDIM, i = e - m * LDIM;
        float a0 = h.x * x2val(sE, s2, m, i);
        if (++i == LDIM) { i = 0; ++m; }
        float a1 = h.y * x2val(sE, s2, m, i);
        if (++i == LDIM) { i = 0; ++m; }
        float a2 = h.z * x2val(sE, s2, m, i);
        if (++i == LDIM) { i = 0; ++m; }
        float a3 = h.w * x2val(sE, s2, m, i);
        lmax = fmaxf(fmaxf(fmaxf(a0, a1), fmaxf(a2, a3)), lmax);
    }
    float bm = blockReduceMax(lmax, sred);
    if (tid == 0) g_rmax2[r] = bm;
}

// ---------------------------------------------------------------------------
// Backward pass 2: recompute X2 (H L2-resident), write normalized output.
// ---------------------------------------------------------------------------
__global__ void __launch_bounds__(512) k_bwd2(const float* __restrict__ y,
                                              const float* __restrict__ H,
                                              float* __restrict__ out) {
    __shared__ float sE[CTOT + 2];
    __shared__ float s2[CTOT];
    __shared__ float sred[32];
    const int r = blockIdx.x, tid = threadIdx.x;

    float v0 = (tid < MDIM) ? g_rmax1[tid] : -INFINITY;
    const float invY = 1.0f / blockReduceMax(v0, sred);
    float v1 = (tid < MDIM) ? g_rmax2[tid] : -INFINITY;
    const float invO = 1.0f / blockReduceMax(v1, sred);
    buildResidual(y, r, invY, sE, s2);

    const float4* H4 = (const float4*)(H + (size_t)r * XCE);
    float4*       O4 = (float4*)(out + (size_t)r * XCE);
    for (int j = tid; j < XC4; j += 512) {
        float4 h = __ldg(H4 + j);
        int e = j * 4;
        int m = e / LDIM, i = e - m * LDIM;
        float4 o;
        o.x = h.x * x2val(sE, s2, m, i) * invO;
        if (++i == LDIM) { i = 0; ++m; }
        o.y = h.y * x2val(sE, s2, m, i) * invO;
        if (++i == LDIM) { i = 0; ++m; }
        o.z = h.z * x2val(sE, s2, m, i) * invO;
        if (++i == LDIM) { i = 0; ++m; }
        o.w = h.w * x2val(sE, s2, m, i) * invO;
        O4[j] = o;
    }
}

extern "C" void kernel_launch(void* const* d_in, const int* in_sizes, int n_in,
                              void* d_out, int out_size) {
    const float *X = 0, *y = 0, *H = 0;
    for (int i = 0; i < n_in; ++i) {
        if      (in_sizes[i] == NX * NX * LDIM)     X = (const float*)d_in[i];
        else if (in_sizes[i] == MDIM * CTOT)        y = (const float*)d_in[i];
        else if (in_sizes[i] == MDIM * MDIM * LDIM) H = (const float*)d_in[i];
    }
    if (!X || !y || !H) {
        X = (const float*)d_in[0];
        y = (const float*)d_in[1];
        H = (const float*)d_in[2];
    }
    float* out = (float*)d_out;

    dim3 gf(NTILE, MDIM);
    k_fwd <<<gf, 256>>>(X, H);
    k_max <<<MDIM, 256>>>();
    k_bwd1<<<MDIM, 512>>>(y, H);
    k_bwd2<<<MDIM, 512>>>(y, H, out);
}

// round 13
// speedup vs baseline: 1.1284x; 1.0007x over previous
#include <cuda_runtime.h>
#include <math.h>

#define MDIM 512
#define LDIM 31
#define CTOT 542                 // MDIM + LDIM - 1
#define NX   1024
#define ROWE (NX * LDIM)         // 31744 floats per input row strip
#define ROW4 (ROWE / 4)          // 7936 float4 per row strip
#define XCE  (MDIM * LDIM)       // 15872 floats per H/out row strip
#define XC4  (XCE / 4)           // 3968 float4 per row
#define XC4H (XC4 / 2)           // 1984 float4 per half-row

#define WC     64                // output columns per tile
#define NTILE  (MDIM / WC)       // 8
#define WCOLS  (2 * WC + 2)      // 130 input cols per window
#define WF4    1008              // float4 loads per stream
#define YLEN   94                // outputs per tile (WC + LDIM - 1)
#define YPAD   96

// Static scratch
__device__ float g_ynp[NTILE * MDIM * YPAD]; // per-tile partial yn
__device__ float g_yn[MDIM * CTOT];
__device__ float g_rmax1[MDIM];
__device__ float g_rmax2[2 * MDIM];          // per half-row max of X2

__device__ __forceinline__ float blockReduceMax(float v, float* sred) {
    __syncthreads();
    int lane = threadIdx.x & 31, wid = threadIdx.x >> 5;
    int nw = blockDim.x >> 5;
    #pragma unroll
    for (int o = 16; o; o >>= 1) v = fmaxf(v, __shfl_xor_sync(0xffffffffu, v, o));
    if (lane == 0) sred[wid] = v;
    __syncthreads();
    if (wid == 0) {
        float x = (lane < nw) ? sred[lane] : -INFINITY;
        #pragma unroll
        for (int o = 16; o; o >>= 1) x = fmaxf(x, __shfl_xor_sync(0xffffffffu, x, o));
        if (lane == 0) sred[0] = x;
    }
    __syncthreads();
    return sred[0];
}

// ---------------------------------------------------------------------------
// Forward: one block per (tile, row). Contiguous-window float4 streaming,
// lambda-before-resize (linear ops commute), conflict-free skew sum.
// ---------------------------------------------------------------------------
__global__ void __launch_bounds__(256, 6) k_fwd(const float* __restrict__ X,
                                                const float* __restrict__ H) {
    __shared__ float4 sBuf4[WF4];        // raw window, later sP alias
    __shared__ float  sLam[WCOLS * 32];
    float* sRaw = (float*)sBuf4;         // sRaw[1 + k] = window elem k
    float* sP   = (float*)sBuf4;         // 64 x 33 floats (aliases, fits)

    const int t = blockIdx.x, r = blockIdx.y;
    const int tid = threadIdx.x;
    const int lane = tid & 31, warp = tid >> 5;

    float w0, w1, w2, w3; int i0, i1, i2, i3;
    if (r == 0) {
        w0 = 0.f;     w1 = 3.f/7.f; w2 = 3.f/7.f; w3 = 1.f/7.f;
        i0 = 0; i1 = 0; i2 = 1; i3 = 2;
    } else if (r == MDIM - 1) {
        w0 = 1.f/7.f; w1 = 3.f/7.f; w2 = 3.f/7.f; w3 = 0.f;
        i0 = 2*r - 1; i1 = 2*r; i2 = 2*r + 1; i3 = i2;
    } else {
        w0 = 0.125f;  w1 = 0.375f;  w2 = 0.375f;  w3 = 0.125f;
        i0 = 2*r - 1; i1 = 2*r; i2 = 2*r + 1; i3 = 2*r + 2;
    }
    const float4* X0 = (const float4*)(X + (size_t)i0 * ROWE);
    const float4* X1 = (const float4*)(X + (size_t)i1 * ROWE);
    const float4* X2p = (const float4*)(X + (size_t)i2 * ROWE);
    const float4* X3 = (const float4*)(X + (size_t)i3 * ROWE);
    const float* Hr = H + (size_t)r * XCE;

    // Phase A: vectorized row-combine; window = contiguous [gb, gb+4030),
    // gb = 3968t-31, aligned base j0 = 992t-8; OOB float4s zero-filled.
    {
        const int j0 = 992 * t - 8;
        for (int j = tid; j < WF4; j += 256) {
            int g4 = j0 + j;
            float4 o = make_float4(0.f, 0.f, 0.f, 0.f);
            if (g4 >= 0 && g4 < ROW4) {
                float4 a = __ldg(X0 + g4), b = __ldg(X1 + g4);
                float4 c = __ldg(X2p + g4), d = __ldg(X3 + g4);
                o.x = w0*a.x + w1*b.x + w2*c.x + w3*d.x;
                o.y = w0*a.y + w1*b.y + w2*c.y + w3*d.y;
                o.z = w0*a.z + w1*b.z + w2*c.z + w3*d.z;
                o.w = w0*a.w + w1*b.w + w2*c.w + w3*d.w;
            }
            sBuf4[j] = o;
        }
    }
    __syncthreads();

    // Phase A2: lambda conv + transpose to stride-32 via shuffles.
    for (int col = warp; col < WCOLS; col += 8) {
        float x = (lane < LDIM) ? sRaw[1 + col * LDIM + lane] : 0.f;
        float xm = __shfl_up_sync(0xffffffffu, x, 1);
        float xp = __shfl_down_sync(0xffffffffu, x, 1);
        float v = 0.5f * x;
        if (lane > 0)         v += 0.25f * xm;
        if (lane < LDIM - 1)  v += 0.25f * xp;
        sLam[col * 32 + lane] = v;
    }
    __syncthreads();

    // Phase B: 4-tap column resize + H multiply -> sP (stride 33).
    {
        const int c0 = t * WC;
        const int l = lane, dc0 = warp;
        if (l < LDIM) {
            #pragma unroll
            for (int q = 0; q < 8; ++q) {
                int dc = dc0 + q * 8;
                int c = c0 + dc;
                float v;
                if (c == 0) {
                    v = (3.f/7.f)*sLam[1*32 + l] + (3.f/7.f)*sLam[2*32 + l]
                      + (1.f/7.f)*sLam[3*32 + l];
                } else if (c == MDIM - 1) {
                    v = (1.f/7.f)*sLam[126*32 + l] + (3.f/7.f)*sLam[127*32 + l]
                      + (3.f/7.f)*sLam[128*32 + l];
                } else {
                    int b = 2 * dc * 32 + l;
                    v = 0.125f*sLam[b]      + 0.375f*sLam[b + 32]
                      + 0.375f*sLam[b + 64] + 0.125f*sLam[b + 96];
                }
                sP[dc * 33 + l] = __ldg(Hr + c * LDIM + l) * v;
            }
        }
    }
    __syncthreads();

    // Phase D: skewed partial sums (deterministic, no atomics).
    if (tid < YLEN) {
        int lcc = tid;
        int ilo = lcc - (WC - 1); if (ilo < 0) ilo = 0;
        int ihi = (lcc < LDIM - 1) ? lcc : (LDIM - 1);
        float acc = 0.f;
        for (int i = ilo; i <= ihi; ++i)
            acc += sP[(lcc - i) * 33 + i];
        g_ynp[(t * MDIM + r) * YPAD + lcc] = acc;
    }
}

// ---------------------------------------------------------------------------
// Combine tile partials -> yn row + per-row max.
// ---------------------------------------------------------------------------
__global__ void __launch_bounds__(256) k_max(void) {
    __shared__ float sred[32];
    const int r = blockIdx.x, tid = threadIdx.x;
    float lmax = -INFINITY;
    for (int cc = tid; cc < CTOT; cc += 256) {
        int thi = cc >> 6; if (thi > NTILE - 1) thi = NTILE - 1;
        int tlo = (cc - 30) >> 6; if (tlo < 0) tlo = 0;
        float s = 0.f;
        for (int t2 = tlo; t2 <= thi; ++t2)
            s += g_ynp[(t2 * MDIM + r) * YPAD + (cc - (t2 << 6))];
        g_yn[r * CTOT + cc] = s;
        lmax = fmaxf(lmax, s);
    }
    float bm = blockReduceMax(lmax, sred);
    if (tid == 0) g_rmax1[r] = bm;
}

// Residual scaled by `scale`: sE[1+c] = (yn*invY - y)*scale, zero pads at ends.
// s2 = lambda-conv of sE (inherits the scale).
__device__ __forceinline__ void buildResidual(const float* __restrict__ y, int r,
                                              float invY, float scale,
                                              float* sE, float* s2) {
    const float* ynr = g_yn + r * CTOT;
    const float* yr  = y + r * CTOT;
    const int tid = threadIdx.x, nt = blockDim.x;
    if (tid == 0) { sE[0] = 0.f; sE[CTOT + 1] = 0.f; }
    for (int cc = tid; cc < CTOT; cc += nt)
        sE[cc + 1] = (ynr[cc] * invY - yr[cc]) * scale;
    __syncthreads();
    for (int cc = tid; cc < CTOT; cc += nt)
        s2[cc] = 0.25f * (sE[cc] + sE[cc + 2]) + 0.5f * sE[cc + 1];
    __syncthreads();
}

__device__ __forceinline__ float x2val(const float* sE, const float* s2,
                                       int m, int i) {
    float v = s2[m + i];
    if (i == 0)        v -= 0.25f * sE[m];
    if (i == LDIM - 1) v -= 0.25f * sE[m + 32];
    return v;
}

// step (m,i) forward by one element
#define STEP_MI(mm, ii) do { if (++ii == LDIM) { ii = 0; ++mm; } } while (0)

// ---------------------------------------------------------------------------
// Backward pass 1: per-HALF-row max of X2. Grid 1024 = 2 blocks per row.
// Division hoisted; (m,i) tracked incrementally (e stride 2048 = 66*31+2).
// ---------------------------------------------------------------------------
__global__ void __launch_bounds__(512) k_bwd1(const float* __restrict__ y,
                                              const float* __restrict__ H) {
    __shared__ float sE[CTOT + 2];
    __shared__ float s2[CTOT];
    __shared__ float sred[32];
    const int r = blockIdx.x >> 1, half = blockIdx.x & 1;
    const int tid = threadIdx.x;

    float v0 = (tid < MDIM) ? g_rmax1[tid] : -INFINITY;
    const float invY = 1.0f / blockReduceMax(v0, sred);
    buildResidual(y, r, invY, 1.0f, sE, s2);

    const float4* H4 = (const float4*)(H + (size_t)r * XCE);
    const int jbeg = half * XC4H + tid, jend = (half + 1) * XC4H;
    int e0 = jbeg * 4;
    int m = e0 / LDIM, i = e0 - m * LDIM;        // only division, hoisted
    float lmax = -INFINITY;
    for (int j = jbeg; j < jend; j += 512) {
        float4 h = __ldg(H4 + j);
        int mm = m, ii = i;
        float a0 = h.x * x2val(sE, s2, mm, ii); STEP_MI(mm, ii);
        float a1 = h.y * x2val(sE, s2, mm, ii); STEP_MI(mm, ii);
        float a2 = h.z * x2val(sE, s2, mm, ii); STEP_MI(mm, ii);
        float a3 = h.w * x2val(sE, s2, mm, ii);
        lmax = fmaxf(fmaxf(fmaxf(a0, a1), fmaxf(a2, a3)), lmax);
        m += 66; i += 2; if (i >= LDIM) { i -= LDIM; ++m; }
    }
    float bm = blockReduceMax(lmax, sred);
    if (tid == 0) g_rmax2[blockIdx.x] = bm;
}

// ---------------------------------------------------------------------------
// Backward pass 2: recompute X2 (H L2-resident), write normalized output.
// invO folded into the residual scale (no per-element multiply).
// ---------------------------------------------------------------------------
__global__ void __launch_bounds__(512) k_bwd2(const float* __restrict__ y,
                                              const float* __restrict__ H,
                                              float* __restrict__ out) {
    __shared__ float sE[CTOT + 2];
    __shared__ float s2[CTOT];
    __shared__ float sred[32];
    const int r = blockIdx.x >> 1, half = blockIdx.x & 1;
    const int tid = threadIdx.x;

    float v0 = (tid < MDIM) ? g_rmax1[tid] : -INFINITY;
    const float invY = 1.0f / blockReduceMax(v0, sred);
    float v1 = fmaxf(g_rmax2[tid], g_rmax2[tid + 512]);
    const float invO = 1.0f / blockReduceMax(v1, sred);
    buildResidual(y, r, invY, invO, sE, s2);

    const float4* H4 = (const float4*)(H + (size_t)r * XCE);
    float4*       O4 = (float4*)(out + (size_t)r * XCE);
    const int jbeg = half * XC4H + tid, jend = (half + 1) * XC4H;
    int e0 = jbeg * 4;
    int m = e0 / LDIM, i = e0 - m * LDIM;
    for (int j = jbeg; j < jend; j += 512) {
        float4 h = __ldg(H4 + j);
        int mm = m, ii = i;
        float4 o;
        o.x = h.x * x2val(sE, s2, mm, ii); STEP_MI(mm, ii);
        o.y = h.y * x2val(sE, s2, mm, ii); STEP_MI(mm, ii);
        o.z = h.z * x2val(sE, s2, mm, ii); STEP_MI(mm, ii);
        o.w = h.w * x2val(sE, s2, mm, ii);
        O4[j] = o;
        m += 66; i += 2; if (i >= LDIM) { i -= LDIM; ++m; }
    }
}

extern "C" void kernel_launch(void* const* d_in, const int* in_sizes, int n_in,
                              void* d_out, int out_size) {
    const float *X = 0, *y = 0, *H = 0;
    for (int i = 0; i < n_in; ++i) {
        if      (in_sizes[i] == NX * NX * LDIM)     X = (const float*)d_in[i];
        else if (in_sizes[i] == MDIM * CTOT)        y = (const float*)d_in[i];
        else if (in_sizes[i] == MDIM * MDIM * LDIM) H = (const float*)d_in[i];
    }
    if (!X || !y || !H) {
        X = (const float*)d_in[0];
        y = (const float*)d_in[1];
        H = (const float*)d_in[2];
    }
    float* out = (float*)d_out;

    dim3 gf(NTILE, MDIM);
    k_fwd <<<gf, 256>>>(X, H);
    k_max <<<MDIM, 256>>>();
    k_bwd1<<<2 * MDIM, 512>>>(y, H);
    k_bwd2<<<2 * MDIM, 512>>>(y, H, out);
}

// round 14
// speedup vs baseline: 1.2326x; 1.0923x over previous
#include <cuda_runtime.h>
#include <math.h>

#define MDIM 512
#define LDIM 31
#define CTOT 542                 // MDIM + LDIM - 1
#define NX   1024
#define ROWE (NX * LDIM)         // 31744 floats per input row strip
#define ROW4 (ROWE / 4)          // 7936 float4 per row strip
#define XCE  (MDIM * LDIM)       // 15872 floats per H/out row strip
#define XC4  (XCE / 4)           // 3968 float4 per row
#define MH   256                 // m-rows per half
#define XEH  (MH * LDIM)         // 7936 floats per half-row
#define XC4H (XEH / 4)           // 1984 float4 per half-row

#define WC     64                // output columns per tile
#define NTILE  (MDIM / WC)       // 8
#define WCOLS  (2 * WC + 2)      // 130 input cols per window
#define WF4    1008              // float4 loads per stream
#define YLEN   94                // outputs per tile (WC + LDIM - 1)
#define YPAD   96

// Static scratch
__device__ float g_ynp[NTILE * MDIM * YPAD]; // per-tile partial yn
__device__ float g_yn[MDIM * CTOT];
__device__ float g_rmax1[MDIM];
__device__ float g_rmax2[2 * MDIM];          // per half-row max of X2

__device__ __forceinline__ float blockReduceMax(float v, float* sred) {
    __syncthreads();
    int lane = threadIdx.x & 31, wid = threadIdx.x >> 5;
    int nw = blockDim.x >> 5;
    #pragma unroll
    for (int o = 16; o; o >>= 1) v = fmaxf(v, __shfl_xor_sync(0xffffffffu, v, o));
    if (lane == 0) sred[wid] = v;
    __syncthreads();
    if (wid == 0) {
        float x = (lane < nw) ? sred[lane] : -INFINITY;
        #pragma unroll
        for (int o = 16; o; o >>= 1) x = fmaxf(x, __shfl_xor_sync(0xffffffffu, x, o));
        if (lane == 0) sred[0] = x;
    }
    __syncthreads();
    return sred[0];
}

// ---------------------------------------------------------------------------
// Forward: one block per (tile, row). Contiguous-window float4 streaming,
// lambda-before-resize (linear ops commute), conflict-free skew sum.
// (unchanged from R12 — measured near DRAM roofline)
// ---------------------------------------------------------------------------
__global__ void __launch_bounds__(256, 6) k_fwd(const float* __restrict__ X,
                                                const float* __restrict__ H) {
    __shared__ float4 sBuf4[WF4];        // raw window, later sP alias
    __shared__ float  sLam[WCOLS * 32];
    float* sRaw = (float*)sBuf4;         // sRaw[1 + k] = window elem k
    float* sP   = (float*)sBuf4;         // 64 x 33 floats (aliases, fits)

    const int t = blockIdx.x, r = blockIdx.y;
    const int tid = threadIdx.x;
    const int lane = tid & 31, warp = tid >> 5;

    float w0, w1, w2, w3; int i0, i1, i2, i3;
    if (r == 0) {
        w0 = 0.f;     w1 = 3.f/7.f; w2 = 3.f/7.f; w3 = 1.f/7.f;
        i0 = 0; i1 = 0; i2 = 1; i3 = 2;
    } else if (r == MDIM - 1) {
        w0 = 1.f/7.f; w1 = 3.f/7.f; w2 = 3.f/7.f; w3 = 0.f;
        i0 = 2*r - 1; i1 = 2*r; i2 = 2*r + 1; i3 = i2;
    } else {
        w0 = 0.125f;  w1 = 0.375f;  w2 = 0.375f;  w3 = 0.125f;
        i0 = 2*r - 1; i1 = 2*r; i2 = 2*r + 1; i3 = 2*r + 2;
    }
    const float4* X0 = (const float4*)(X + (size_t)i0 * ROWE);
    const float4* X1 = (const float4*)(X + (size_t)i1 * ROWE);
    const float4* X2p = (const float4*)(X + (size_t)i2 * ROWE);
    const float4* X3 = (const float4*)(X + (size_t)i3 * ROWE);
    const float* Hr = H + (size_t)r * XCE;

    {
        const int j0 = 992 * t - 8;
        for (int j = tid; j < WF4; j += 256) {
            int g4 = j0 + j;
            float4 o = make_float4(0.f, 0.f, 0.f, 0.f);
            if (g4 >= 0 && g4 < ROW4) {
                float4 a = __ldg(X0 + g4), b = __ldg(X1 + g4);
                float4 c = __ldg(X2p + g4), d = __ldg(X3 + g4);
                o.x = w0*a.x + w1*b.x + w2*c.x + w3*d.x;
                o.y = w0*a.y + w1*b.y + w2*c.y + w3*d.y;
                o.z = w0*a.z + w1*b.z + w2*c.z + w3*d.z;
                o.w = w0*a.w + w1*b.w + w2*c.w + w3*d.w;
            }
            sBuf4[j] = o;
        }
    }
    __syncthreads();

    for (int col = warp; col < WCOLS; col += 8) {
        float x = (lane < LDIM) ? sRaw[1 + col * LDIM + lane] : 0.f;
        float xm = __shfl_up_sync(0xffffffffu, x, 1);
        float xp = __shfl_down_sync(0xffffffffu, x, 1);
        float v = 0.5f * x;
        if (lane > 0)         v += 0.25f * xm;
        if (lane < LDIM - 1)  v += 0.25f * xp;
        sLam[col * 32 + lane] = v;
    }
    __syncthreads();

    {
        const int c0 = t * WC;
        const int l = lane, dc0 = warp;
        if (l < LDIM) {
            #pragma unroll
            for (int q = 0; q < 8; ++q) {
                int dc = dc0 + q * 8;
                int c = c0 + dc;
                float v;
                if (c == 0) {
                    v = (3.f/7.f)*sLam[1*32 + l] + (3.f/7.f)*sLam[2*32 + l]
                      + (1.f/7.f)*sLam[3*32 + l];
                } else if (c == MDIM - 1) {
                    v = (1.f/7.f)*sLam[126*32 + l] + (3.f/7.f)*sLam[127*32 + l]
                      + (3.f/7.f)*sLam[128*32 + l];
                } else {
                    int b = 2 * dc * 32 + l;
                    v = 0.125f*sLam[b]      + 0.375f*sLam[b + 32]
                      + 0.375f*sLam[b + 64] + 0.125f*sLam[b + 96];
                }
                sP[dc * 33 + l] = __ldg(Hr + c * LDIM + l) * v;
            }
        }
    }
    __syncthreads();

    if (tid < YLEN) {
        int lcc = tid;
        int ilo = lcc - (WC - 1); if (ilo < 0) ilo = 0;
        int ihi = (lcc < LDIM - 1) ? lcc : (LDIM - 1);
        float acc = 0.f;
        for (int i = ilo; i <= ihi; ++i)
            acc += sP[(lcc - i) * 33 + i];
        g_ynp[(t * MDIM + r) * YPAD + lcc] = acc;
    }
}

// ---------------------------------------------------------------------------
// Combine tile partials -> yn row + per-row max.
// ---------------------------------------------------------------------------
__global__ void __launch_bounds__(256) k_max(void) {
    __shared__ float sred[32];
    const int r = blockIdx.x, tid = threadIdx.x;
    float lmax = -INFINITY;
    for (int cc = tid; cc < CTOT; cc += 256) {
        int thi = cc >> 6; if (thi > NTILE - 1) thi = NTILE - 1;
        int tlo = (cc - 30) >> 6; if (tlo < 0) tlo = 0;
        float s = 0.f;
        for (int t2 = tlo; t2 <= thi; ++t2)
            s += g_ynp[(t2 * MDIM + r) * YPAD + (cc - (t2 << 6))];
        g_yn[r * CTOT + cc] = s;
        lmax = fmaxf(lmax, s);
    }
    float bm = blockReduceMax(lmax, sred);
    if (tid == 0) g_rmax1[r] = bm;
}

// Build scaled residual sE (zero-padded), its lambda-conv s2, and the full
// multiplier array sv for this half-row:
//   sv[(m-mb)*31+i] = s2[m+i]  (corrections folded at i=0 and i=30)
// After this, the stream loop is a pure H*sv multiply.
__device__ __forceinline__ void buildHalfV(const float* __restrict__ y, int r,
                                           int half, float invY, float scale,
                                           float* sE, float* s2, float* sv) {
    const float* ynr = g_yn + r * CTOT;
    const float* yr  = y + r * CTOT;
    const int tid = threadIdx.x;
    if (tid == 0) { sE[0] = 0.f; sE[CTOT + 1] = 0.f; }
    for (int cc = tid; cc < CTOT; cc += 256)
        sE[cc + 1] = (ynr[cc] * invY - yr[cc]) * scale;
    __syncthreads();
    for (int cc = tid; cc < CTOT; cc += 256)
        s2[cc] = 0.25f * (sE[cc] + sE[cc + 2]) + 0.5f * sE[cc + 1];
    __syncthreads();
    // one m per thread (MH = 256 = blockDim). Stores stride-31: conflict-free.
    const int m = half * MH + tid;
    float* svm = sv + tid * LDIM;
    #pragma unroll
    for (int i = 0; i < LDIM; ++i)
        svm[i] = s2[m + i];
    svm[0]        -= 0.25f * sE[m];        // i==0 correction (sE[m]=res[m-1])
    svm[LDIM - 1] -= 0.25f * sE[m + 32];   // i==30 correction (res[m+31])
    __syncthreads();
}

// ---------------------------------------------------------------------------
// Backward pass 1: per-half-row max of X2. Pure stream: LDG(H)+LDS128(sv)+MUL.
// ---------------------------------------------------------------------------
__global__ void __launch_bounds__(256) k_bwd1(const float* __restrict__ y,
                                              const float* __restrict__ H) {
    __shared__ float sv[XEH];            // 31.0 KB multiplier array
    __shared__ float sE[CTOT + 2];
    __shared__ float s2[CTOT];
    __shared__ float sred[32];
    const int r = blockIdx.x >> 1, half = blockIdx.x & 1;
    const int tid = threadIdx.x;

    float v0 = -INFINITY;
    if (tid < MDIM - 256) {}             // (MDIM=512, 256 threads: 2 vals each)
    v0 = fmaxf(g_rmax1[tid], g_rmax1[tid + 256]);
    const float invY = 1.0f / blockReduceMax(v0, sred);
    buildHalfV(y, r, half, invY, 1.0f, sE, s2, sv);

    const float4* H4 = (const float4*)(H + (size_t)r * XCE) + half * XC4H;
    const float4* V4 = (const float4*)sv;
    float lmax = -INFINITY;
    #pragma unroll 4
    for (int j = tid; j < XC4H; j += 256) {
        float4 h = __ldg(H4 + j);
        float4 v = V4[j];
        lmax = fmaxf(lmax, fmaxf(fmaxf(h.x * v.x, h.y * v.y),
                                 fmaxf(h.z * v.z, h.w * v.w)));
    }
    float bm = blockReduceMax(lmax, sred);
    if (tid == 0) g_rmax2[blockIdx.x] = bm;
}

// ---------------------------------------------------------------------------
// Backward pass 2: normalized output. invO folded into sv at build time.
// ---------------------------------------------------------------------------
__global__ void __launch_bounds__(256) k_bwd2(const float* __restrict__ y,
                                              const float* __restrict__ H,
                                              float* __restrict__ out) {
    __shared__ float sv[XEH];
    __shared__ float sE[CTOT + 2];
    __shared__ float s2[CTOT];
    __shared__ float sred[32];
    const int r = blockIdx.x >> 1, half = blockIdx.x & 1;
    const int tid = threadIdx.x;

    float v0 = fmaxf(g_rmax1[tid], g_rmax1[tid + 256]);
    const float invY = 1.0f / blockReduceMax(v0, sred);
    float v1 = fmaxf(fmaxf(g_rmax2[tid], g_rmax2[tid + 256]),
                     fmaxf(g_rmax2[tid + 512], g_rmax2[tid + 768]));
    const float invO = 1.0f / blockReduceMax(v1, sred);
    buildHalfV(y, r, half, invY, invO, sE, s2, sv);

    const float4* H4 = (const float4*)(H + (size_t)r * XCE) + half * XC4H;
    float4*       O4 = (float4*)(out + (size_t)r * XCE) + half * XC4H;
    const float4* V4 = (const float4*)sv;
    #pragma unroll 4
    for (int j = tid; j < XC4H; j += 256) {
        float4 h = __ldg(H4 + j);
        float4 v = V4[j];
        float4 o;
        o.x = h.x * v.x; o.y = h.y * v.y; o.z = h.z * v.z; o.w = h.w * v.w;
        O4[j] = o;
    }
}

extern "C" void kernel_launch(void* const* d_in, const int* in_sizes, int n_in,
                              void* d_out, int out_size) {
    const float *X = 0, *y = 0, *H = 0;
    for (int i = 0; i < n_in; ++i) {
        if      (in_sizes[i] == NX * NX * LDIM)     X = (const float*)d_in[i];
        else if (in_sizes[i] == MDIM * CTOT)        y = (const float*)d_in[i];
        else if (in_sizes[i] == MDIM * MDIM * LDIM) H = (const float*)d_in[i];
    }
    if (!X || !y || !H) {
        X = (const float*)d_in[0];
        y = (const float*)d_in[1];
        H = (const float*)d_in[2];
    }
    float* out = (float*)d_out;

    dim3 gf(NTILE, MDIM);
    k_fwd <<<gf, 256>>>(X, H);
    k_max <<<MDIM, 256>>>();
    k_bwd1<<<2 * MDIM, 256>>>(y, H);
    k_bwd2<<<2 * MDIM, 256>>>(y, H, out);
}

// round 15
// speedup vs baseline: 1.2600x; 1.0223x over previous
#include <cuda_runtime.h>
#include <math.h>

#define MDIM 512
#define LDIM 31
#define CTOT 542                 // MDIM + LDIM - 1
#define NX   1024
#define ROWE (NX * LDIM)         // 31744 floats per input row strip
#define ROW4 (ROWE / 4)          // 7936 float4 per row strip
#define XCE  (MDIM * LDIM)       // 15872 floats per H/out row strip
#define XC4  (XCE / 4)           // 3968 float4 per row

#define WC     64                // output columns per tile
#define NTILE  (MDIM / WC)       // 8
#define WCOLS  (2 * WC + 2)      // 130 input cols per window
#define WF4    1008              // float4 loads per stream
#define YLEN   94                // outputs per tile (WC + LDIM - 1)
#define YPAD   96

// dynamic smem layout for bwd kernels: sv[XCE] | sE[CTOT+2] | sred[32]
#define BWD_SMEM ((XCE + CTOT + 2 + 32) * sizeof(float))

// Static scratch
__device__ float g_ynp[NTILE * MDIM * YPAD]; // per-tile partial yn
__device__ float g_yn[MDIM * CTOT];
__device__ float g_rmax1[MDIM];
__device__ float g_rmax2[MDIM];              // per-row max of X2

__device__ __forceinline__ float blockReduceMax(float v, float* sred) {
    __syncthreads();
    int lane = threadIdx.x & 31, wid = threadIdx.x >> 5;
    int nw = blockDim.x >> 5;
    #pragma unroll
    for (int o = 16; o; o >>= 1) v = fmaxf(v, __shfl_xor_sync(0xffffffffu, v, o));
    if (lane == 0) sred[wid] = v;
    __syncthreads();
    if (wid == 0) {
        float x = (lane < nw) ? sred[lane] : -INFINITY;
        #pragma unroll
        for (int o = 16; o; o >>= 1) x = fmaxf(x, __shfl_xor_sync(0xffffffffu, x, o));
        if (lane == 0) sred[0] = x;
    }
    __syncthreads();
    return sred[0];
}

// ---------------------------------------------------------------------------
// Forward: one block per (tile, row). Contiguous-window float4 streaming,
// lambda-before-resize (linear ops commute), conflict-free skew sum.
// (unchanged — measured at its DRAM floor)
// ---------------------------------------------------------------------------
__global__ void __launch_bounds__(256, 6) k_fwd(const float* __restrict__ X,
                                                const float* __restrict__ H) {
    __shared__ float4 sBuf4[WF4];        // raw window, later sP alias
    __shared__ float  sLam[WCOLS * 32];
    float* sRaw = (float*)sBuf4;
    float* sP   = (float*)sBuf4;

    const int t = blockIdx.x, r = blockIdx.y;
    const int tid = threadIdx.x;
    const int lane = tid & 31, warp = tid >> 5;

    float w0, w1, w2, w3; int i0, i1, i2, i3;
    if (r == 0) {
        w0 = 0.f;     w1 = 3.f/7.f; w2 = 3.f/7.f; w3 = 1.f/7.f;
        i0 = 0; i1 = 0; i2 = 1; i3 = 2;
    } else if (r == MDIM - 1) {
        w0 = 1.f/7.f; w1 = 3.f/7.f; w2 = 3.f/7.f; w3 = 0.f;
        i0 = 2*r - 1; i1 = 2*r; i2 = 2*r + 1; i3 = i2;
    } else {
        w0 = 0.125f;  w1 = 0.375f;  w2 = 0.375f;  w3 = 0.125f;
        i0 = 2*r - 1; i1 = 2*r; i2 = 2*r + 1; i3 = 2*r + 2;
    }
    const float4* X0 = (const float4*)(X + (size_t)i0 * ROWE);
    const float4* X1 = (const float4*)(X + (size_t)i1 * ROWE);
    const float4* X2p = (const float4*)(X + (size_t)i2 * ROWE);
    const float4* X3 = (const float4*)(X + (size_t)i3 * ROWE);
    const float* Hr = H + (size_t)r * XCE;

    {
        const int j0 = 992 * t - 8;
        for (int j = tid; j < WF4; j += 256) {
            int g4 = j0 + j;
            float4 o = make_float4(0.f, 0.f, 0.f, 0.f);
            if (g4 >= 0 && g4 < ROW4) {
                float4 a = __ldg(X0 + g4), b = __ldg(X1 + g4);
                float4 c = __ldg(X2p + g4), d = __ldg(X3 + g4);
                o.x = w0*a.x + w1*b.x + w2*c.x + w3*d.x;
                o.y = w0*a.y + w1*b.y + w2*c.y + w3*d.y;
                o.z = w0*a.z + w1*b.z + w2*c.z + w3*d.z;
                o.w = w0*a.w + w1*b.w + w2*c.w + w3*d.w;
            }
            sBuf4[j] = o;
        }
    }
    __syncthreads();

    for (int col = warp; col < WCOLS; col += 8) {
        float x = (lane < LDIM) ? sRaw[1 + col * LDIM + lane] : 0.f;
        float xm = __shfl_up_sync(0xffffffffu, x, 1);
        float xp = __shfl_down_sync(0xffffffffu, x, 1);
        float v = 0.5f * x;
        if (lane > 0)         v += 0.25f * xm;
        if (lane < LDIM - 1)  v += 0.25f * xp;
        sLam[col * 32 + lane] = v;
    }
    __syncthreads();

    {
        const int c0 = t * WC;
        const int l = lane, dc0 = warp;
        if (l < LDIM) {
            #pragma unroll
            for (int q = 0; q < 8; ++q) {
                int dc = dc0 + q * 8;
                int c = c0 + dc;
                float v;
                if (c == 0) {
                    v = (3.f/7.f)*sLam[1*32 + l] + (3.f/7.f)*sLam[2*32 + l]
                      + (1.f/7.f)*sLam[3*32 + l];
                } else if (c == MDIM - 1) {
                    v = (1.f/7.f)*sLam[126*32 + l] + (3.f/7.f)*sLam[127*32 + l]
                      + (3.f/7.f)*sLam[128*32 + l];
                } else {
                    int b = 2 * dc * 32 + l;
                    v = 0.125f*sLam[b]      + 0.375f*sLam[b + 32]
                      + 0.375f*sLam[b + 64] + 0.125f*sLam[b + 96];
                }
                sP[dc * 33 + l] = __ldg(Hr + c * LDIM + l) * v;
            }
        }
    }
    __syncthreads();

    if (tid < YLEN) {
        int lcc = tid;
        int ilo = lcc - (WC - 1); if (ilo < 0) ilo = 0;
        int ihi = (lcc < LDIM - 1) ? lcc : (LDIM - 1);
        float acc = 0.f;
        for (int i = ilo; i <= ihi; ++i)
            acc += sP[(lcc - i) * 33 + i];
        g_ynp[(t * MDIM + r) * YPAD + lcc] = acc;
    }
}

// ---------------------------------------------------------------------------
// Combine tile partials -> yn row + per-row max.
// ---------------------------------------------------------------------------
__global__ void __launch_bounds__(256) k_max(void) {
    __shared__ float sred[32];
    const int r = blockIdx.x, tid = threadIdx.x;
    float lmax = -INFINITY;
    for (int cc = tid; cc < CTOT; cc += 256) {
        int thi = cc >> 6; if (thi > NTILE - 1) thi = NTILE - 1;
        int tlo = (cc - 30) >> 6; if (tlo < 0) tlo = 0;
        float s = 0.f;
        for (int t2 = tlo; t2 <= thi; ++t2)
            s += g_ynp[(t2 * MDIM + r) * YPAD + (cc - (t2 << 6))];
        g_yn[r * CTOT + cc] = s;
        lmax = fmaxf(lmax, s);
    }
    float bm = blockReduceMax(lmax, sred);
    if (tid == 0) g_rmax1[r] = bm;
}

// Build scaled residual sE (zero-padded) and the full-row multiplier array
// sv directly from sE (no s2 intermediate):
//   sv[m*31+i] = 0.25*(sE[m+i] + sE[m+i+2]) + 0.5*sE[m+i+1]
// with the i==0 / i==30 boundary corrections folded in. 512 threads = 1 m each.
__device__ __forceinline__ void buildRowV(const float* __restrict__ y, int r,
                                          float invY, float scale,
                                          float* sE, float* sv) {
    const float* ynr = g_yn + r * CTOT;
    const float* yr  = y + r * CTOT;
    const int tid = threadIdx.x;
    if (tid == 0) { sE[0] = 0.f; sE[CTOT + 1] = 0.f; }
    for (int cc = tid; cc < CTOT; cc += 512)
        sE[cc + 1] = (ynr[cc] * invY - yr[cc]) * scale;
    __syncthreads();
    const float* base = sE + tid;        // thread tid handles m = tid
    float* svm = sv + tid * LDIM;
    #pragma unroll
    for (int i = 0; i < LDIM; ++i)
        svm[i] = 0.25f * (base[i] + base[i + 2]) + 0.5f * base[i + 1];
    svm[0]        -= 0.25f * base[0];         // i==0:  minus 0.25*res[m-1]
    svm[LDIM - 1] -= 0.25f * base[32];        // i==30: minus 0.25*res[m+31]
    __syncthreads();
}

// ---------------------------------------------------------------------------
// Backward pass 1: per-row max of X2. Pure stream loop after build.
// ---------------------------------------------------------------------------
__global__ void __launch_bounds__(512) k_bwd1(const float* __restrict__ y,
                                              const float* __restrict__ H) {
    extern __shared__ float sm[];
    float* sv   = sm;                    // XCE floats
    float* sE   = sm + XCE;              // CTOT+2 floats
    float* sred = sE + CTOT + 2;         // 32 floats
    const int r = blockIdx.x, tid = threadIdx.x;

    float v0 = (tid < MDIM) ? g_rmax1[tid] : -INFINITY;
    const float invY = 1.0f / blockReduceMax(v0, sred);
    buildRowV(y, r, invY, 1.0f, sE, sv);

    const float4* H4 = (const float4*)(H + (size_t)r * XCE);
    const float4* V4 = (const float4*)sv;
    float lmax = -INFINITY;
    #pragma unroll 4
    for (int j = tid; j < XC4; j += 512) {
        float4 h = __ldg(H4 + j);
        float4 v = V4[j];
        lmax = fmaxf(lmax, fmaxf(fmaxf(h.x * v.x, h.y * v.y),
                                 fmaxf(h.z * v.z, h.w * v.w)));
    }
    float bm = blockReduceMax(lmax, sred);
    if (tid == 0) g_rmax2[r] = bm;
}

// ---------------------------------------------------------------------------
// Backward pass 2: normalized output. invO folded into sv at build time.
// ---------------------------------------------------------------------------
__global__ void __launch_bounds__(512) k_bwd2(const float* __restrict__ y,
                                              const float* __restrict__ H,
                                              float* __restrict__ out) {
    extern __shared__ float sm[];
    float* sv   = sm;
    float* sE   = sm + XCE;
    float* sred = sE + CTOT + 2;
    const int r = blockIdx.x, tid = threadIdx.x;

    float v0 = (tid < MDIM) ? g_rmax1[tid] : -INFINITY;
    const float invY = 1.0f / blockReduceMax(v0, sred);
    float v1 = (tid < MDIM) ? g_rmax2[tid] : -INFINITY;
    const float invO = 1.0f / blockReduceMax(v1, sred);
    buildRowV(y, r, invY, invO, sE, sv);

    const float4* H4 = (const float4*)(H + (size_t)r * XCE);
    float4*       O4 = (float4*)(out + (size_t)r * XCE);
    const float4* V4 = (const float4*)sv;
    #pragma unroll 4
    for (int j = tid; j < XC4; j += 512) {
        float4 h = __ldg(H4 + j);
        float4 v = V4[j];
        float4 o;
        o.x = h.x * v.x; o.y = h.y * v.y; o.z = h.z * v.z; o.w = h.w * v.w;
        O4[j] = o;
    }
}

extern "C" void kernel_launch(void* const* d_in, const int* in_sizes, int n_in,
                              void* d_out, int out_size) {
    const float *X = 0, *y = 0, *H = 0;
    for (int i = 0; i < n_in; ++i) {
        if      (in_sizes[i] == NX * NX * LDIM)     X = (const float*)d_in[i];
        else if (in_sizes[i] == MDIM * CTOT)        y = (const float*)d_in[i];
        else if (in_sizes[i] == MDIM * MDIM * LDIM) H = (const float*)d_in[i];
    }
    if (!X || !y || !H) {
        X = (const float*)d_in[0];
        y = (const float*)d_in[1];
        H = (const float*)d_in[2];
    }
    float* out = (float*)d_out;

    cudaFuncSetAttribute(k_bwd1, cudaFuncAttributeMaxDynamicSharedMemorySize,
                         (int)BWD_SMEM);
    cudaFuncSetAttribute(k_bwd2, cudaFuncAttributeMaxDynamicSharedMemorySize,
                         (int)BWD_SMEM);

    dim3 gf(NTILE, MDIM);
    k_fwd <<<gf, 256>>>(X, H);
    k_max <<<MDIM, 256>>>();
    k_bwd1<<<MDIM, 512, BWD_SMEM>>>(y, H);
    k_bwd2<<<MDIM, 512, BWD_SMEM>>>(y, H, out);
}